// round 15
// baseline (speedup 1.0000x reference)
#include <cuda_runtime.h>
#include <cuda_bf16.h>

// LIF neuron: x_seq (T=64, B=32, F=8192) fp32 -> (spike_seq, mem_seq) each (T,B,F).
// FINAL — converged configuration; identical source measured 37.38, 37.38,
// 35.90 us across three runs (bench noise >= 1.5 us). Best of 9 structurally
// distinct designs over 14 rounds:
//   - PF=8 register prefetch ring of LDG.128 (MLP=8 covers DRAM latency)
//   - 1024 x 64 grid (6.92 avg vs 7 max blocks/SM, ~1% wave imbalance)
//   - loads: ld.global.nc + L2::evict_last cache_hint
//   - stores: st.global.wt
// Limiter: 192 MiB compulsory DRAM traffic per replay at ~5.4-5.9 TB/s
// sustained (1R:2W mixed-stream HBM3e floor). SM side never saturates in any
// shape; all L2-retention mechanisms (load hints, store hints, evict_last v8
// allocation, TMA bulk reads) tested and ineffective on this part/harness.

static constexpr int T  = 64;
static constexpr int BF = 32 * 8192;      // 262144 lanes
static constexpr int N4 = BF / 4;         // 65536 float4 lanes
static constexpr int PF = 8;              // outstanding LDG.128 per thread

__device__ __forceinline__ unsigned long long make_policy_evict_last() {
    unsigned long long pol;
    asm("createpolicy.fractional.L2::evict_last.b64 %0, 1.0;" : "=l"(pol));
    return pol;
}

__device__ __forceinline__ float4 ldg_keep(const float4* p, unsigned long long pol) {
    float4 v;
    asm volatile("ld.global.nc.L2::cache_hint.v4.f32 {%0,%1,%2,%3}, [%4], %5;"
                 : "=f"(v.x), "=f"(v.y), "=f"(v.z), "=f"(v.w)
                 : "l"(p), "l"(pol));
    return v;
}

__device__ __forceinline__ void stg_wt(float4* p, float4 v) {
    asm volatile("st.global.wt.v4.f32 [%0], {%1,%2,%3,%4};"
                 :: "l"(p), "f"(v.x), "f"(v.y), "f"(v.z), "f"(v.w)
                 : "memory");
}

__global__ __launch_bounds__(64) void lif_kernel(
    const float4* __restrict__ x,     // [T, N4]
    float*        __restrict__ out)   // [2, T, N4*4] : spike then mem
{
    const int lane = blockIdx.x * 64 + threadIdx.x;

    const unsigned long long pol_ld = make_policy_evict_last();

    float4* spike_out = reinterpret_cast<float4*>(out);
    float4* mem_out   = reinterpret_cast<float4*>(out) + (size_t)T * N4;

    // Prime the prefetch ring: 8 LDG.128 in flight before any compute.
    float4 buf[PF];
    #pragma unroll
    for (int i = 0; i < PF; i++)
        buf[i] = ldg_keep(&x[(size_t)i * N4 + lane], pol_ld);

    float mx = 0.0f, my = 0.0f, mz = 0.0f, mw = 0.0f;

    #pragma unroll
    for (int t = 0; t < T; t++) {
        const float4 xv = buf[t & (PF - 1)];

        if (t + PF < T)
            buf[t & (PF - 1)] = ldg_keep(&x[(size_t)(t + PF) * N4 + lane], pol_ld);

        // mem = mem*0.5 + x   (*0.5 is exact, fma == mul+add bitwise)
        mx = __fmaf_rn(mx, 0.5f, xv.x);
        my = __fmaf_rn(my, 0.5f, xv.y);
        mz = __fmaf_rn(mz, 0.5f, xv.z);
        mw = __fmaf_rn(mw, 0.5f, xv.w);

        float4 s;
        s.x = (mx >= 1.0f) ? 1.0f : 0.0f;
        s.y = (my >= 1.0f) ? 1.0f : 0.0f;
        s.z = (mz >= 1.0f) ? 1.0f : 0.0f;
        s.w = (mw >= 1.0f) ? 1.0f : 0.0f;

        // reset: mem = 0 where spiked (V_RESET = 0)
        mx = (s.x != 0.0f) ? 0.0f : mx;
        my = (s.y != 0.0f) ? 0.0f : my;
        mz = (s.z != 0.0f) ? 0.0f : mz;
        mw = (s.w != 0.0f) ? 0.0f : mw;

        const float4 m = {mx, my, mz, mw};

        stg_wt(&spike_out[(size_t)t * N4 + lane], s);
        stg_wt(&mem_out  [(size_t)t * N4 + lane], m);
    }
}

extern "C" void kernel_launch(void* const* d_in, const int* in_sizes, int n_in,
                              void* d_out, int out_size) {
    const float4* x = reinterpret_cast<const float4*>(d_in[0]);
    float* out = reinterpret_cast<float*>(d_out);

    const int threads = 64;
    const int blocks  = N4 / threads;   // 1024 blocks
    lif_kernel<<<blocks, threads>>>(x, out);
}

// round 16
// speedup vs baseline: 1.0452x; 1.0452x over previous
#include <cuda_runtime.h>
#include <cuda_bf16.h>

// LIF neuron: x_seq (T=64, B=32, F=8192) fp32 -> (spike_seq, mem_seq) each (T,B,F).
// FINAL — converged configuration; identical source measured 37.38 / 37.38 /
// 35.90 / 36.96 us (mean 36.9, sigma ~0.7). Best of 9 structurally distinct
// designs over 15 rounds:
//   - PF=8 register prefetch ring of LDG.128 (MLP=8 covers DRAM latency)
//   - 1024 x 64 grid (6.92 avg vs 7 max blocks/SM, ~1% wave imbalance)
//   - loads: ld.global.nc + L2::evict_last cache_hint
//   - stores: st.global.wt
// Binding limit: ~384 MiB LTS traffic per replay at ~10.5 TB/s (~95% of the
// measured path-independent LTS cap), equivalently ~5.4-5.9 TB/s DRAM on a
// 1R:2W mix. Zero removable bytes (fp32 contract, single pass, L2 cross-replay
// retention unavailable: persisting carveout 0, device limits locked). SM side
// never saturates in any tested shape.

static constexpr int T  = 64;
static constexpr int BF = 32 * 8192;      // 262144 lanes
static constexpr int N4 = BF / 4;         // 65536 float4 lanes
static constexpr int PF = 8;              // outstanding LDG.128 per thread

__device__ __forceinline__ unsigned long long make_policy_evict_last() {
    unsigned long long pol;
    asm("createpolicy.fractional.L2::evict_last.b64 %0, 1.0;" : "=l"(pol));
    return pol;
}

__device__ __forceinline__ float4 ldg_keep(const float4* p, unsigned long long pol) {
    float4 v;
    asm volatile("ld.global.nc.L2::cache_hint.v4.f32 {%0,%1,%2,%3}, [%4], %5;"
                 : "=f"(v.x), "=f"(v.y), "=f"(v.z), "=f"(v.w)
                 : "l"(p), "l"(pol));
    return v;
}

__device__ __forceinline__ void stg_wt(float4* p, float4 v) {
    asm volatile("st.global.wt.v4.f32 [%0], {%1,%2,%3,%4};"
                 :: "l"(p), "f"(v.x), "f"(v.y), "f"(v.z), "f"(v.w)
                 : "memory");
}

__global__ __launch_bounds__(64) void lif_kernel(
    const float4* __restrict__ x,     // [T, N4]
    float*        __restrict__ out)   // [2, T, N4*4] : spike then mem
{
    const int lane = blockIdx.x * 64 + threadIdx.x;

    const unsigned long long pol_ld = make_policy_evict_last();

    float4* spike_out = reinterpret_cast<float4*>(out);
    float4* mem_out   = reinterpret_cast<float4*>(out) + (size_t)T * N4;

    // Prime the prefetch ring: 8 LDG.128 in flight before any compute.
    float4 buf[PF];
    #pragma unroll
    for (int i = 0; i < PF; i++)
        buf[i] = ldg_keep(&x[(size_t)i * N4 + lane], pol_ld);

    float mx = 0.0f, my = 0.0f, mz = 0.0f, mw = 0.0f;

    #pragma unroll
    for (int t = 0; t < T; t++) {
        const float4 xv = buf[t & (PF - 1)];

        if (t + PF < T)
            buf[t & (PF - 1)] = ldg_keep(&x[(size_t)(t + PF) * N4 + lane], pol_ld);

        // mem = mem*0.5 + x   (*0.5 is exact, fma == mul+add bitwise)
        mx = __fmaf_rn(mx, 0.5f, xv.x);
        my = __fmaf_rn(my, 0.5f, xv.y);
        mz = __fmaf_rn(mz, 0.5f, xv.z);
        mw = __fmaf_rn(mw, 0.5f, xv.w);

        float4 s;
        s.x = (mx >= 1.0f) ? 1.0f : 0.0f;
        s.y = (my >= 1.0f) ? 1.0f : 0.0f;
        s.z = (mz >= 1.0f) ? 1.0f : 0.0f;
        s.w = (mw >= 1.0f) ? 1.0f : 0.0f;

        // reset: mem = 0 where spiked (V_RESET = 0)
        mx = (s.x != 0.0f) ? 0.0f : mx;
        my = (s.y != 0.0f) ? 0.0f : my;
        mz = (s.z != 0.0f) ? 0.0f : mz;
        mw = (s.w != 0.0f) ? 0.0f : mw;

        const float4 m = {mx, my, mz, mw};

        stg_wt(&spike_out[(size_t)t * N4 + lane], s);
        stg_wt(&mem_out  [(size_t)t * N4 + lane], m);
    }
}

extern "C" void kernel_launch(void* const* d_in, const int* in_sizes, int n_in,
                              void* d_out, int out_size) {
    const float4* x = reinterpret_cast<const float4*>(d_in[0]);
    float* out = reinterpret_cast<float*>(d_out);

    const int threads = 64;
    const int blocks  = N4 / threads;   // 1024 blocks
    lif_kernel<<<blocks, threads>>>(x, out);
}